// round 1
// baseline (speedup 1.0000x reference)
#include <cuda_runtime.h>
#include <math.h>

#define Bn 65536
#define Dt 768
#define Dim 2048
#define Dd 300

// small precomputed scratch (allocation-free: __device__ globals)
__device__ float g_WkT[3 * Dd * Dd];
__device__ float g_A[3 * Dd * Dd];
__device__ float g_w[3 * Dd];
__device__ float g_c[3];

// transpose a [300,300] matrix: out[d*300+j] = in[j*300+d]
__global__ void k_transpose(const float* __restrict__ in, float* __restrict__ out) {
    int idx = blockIdx.x * 256 + threadIdx.x;
    if (idx < Dd * Dd) {
        int j = idx / Dd, d = idx % Dd;
        out[d * Dd + j] = in[idx];
    }
}

// w[i] = sum_d Wq[i,d]*bk[d] + Wk[i,d]*bq[d] ;  c = bq.bk
__global__ void k_wc(const float* __restrict__ Wq, const float* __restrict__ bq,
                     const float* __restrict__ Wk, const float* __restrict__ bk,
                     float* __restrict__ w_out, float* __restrict__ c_out) {
    int i = threadIdx.x;
    __shared__ float sred[320];
    if (i < Dd) {
        float s = 0.f;
        for (int d = 0; d < Dd; d++)
            s += Wq[i * Dd + d] * bk[d] + Wk[i * Dd + d] * bq[d];
        w_out[i] = s;
    }
    sred[i] = (i < Dd) ? bq[i] * bk[i] : 0.f;
    __syncthreads();
    for (int s = 256; s > 0; s >>= 1) {
        if (i < s && i + s < 320) sred[i] += sred[i + s];
        __syncthreads();
    }
    if (i == 0) *c_out = sred[0];
}

// out[M,300] = X[M,K] @ W[K,300] (+ bias). CTA: 32 rows x 300 cols, 320 threads.
template <int K, bool GUARD>
__global__ void __launch_bounds__(320, 2)
k_gemm(const float* __restrict__ X, const float* __restrict__ W,
       const float* __restrict__ bias, float* __restrict__ out, int M) {
    constexpr int TM = 32, KB = 32;
    __shared__ float xs[TM][KB];
    const int tid = threadIdx.x;
    const int j = tid;                 // output column
    const int row0 = blockIdx.x * TM;
    float acc[TM];
#pragma unroll
    for (int r = 0; r < TM; r++) acc[r] = 0.f;
    const int lr = tid >> 3, lk = (tid & 7) << 2;  // loader mapping (256 float4s)

    for (int k0 = 0; k0 < K; k0 += KB) {
        __syncthreads();
        if (tid < 256) {
            float4 v = make_float4(0.f, 0.f, 0.f, 0.f);
            int row = row0 + lr;
            bool okr = (!GUARD) || (row < M);
            bool okk = (K % KB == 0) || (k0 + lk < K);
            if (okr && okk)
                v = *reinterpret_cast<const float4*>(&X[(size_t)row * K + k0 + lk]);
            *reinterpret_cast<float4*>(&xs[lr][lk]) = v;
        }
        __syncthreads();
        if (j < Dd) {
#pragma unroll
            for (int kq = 0; kq < KB; kq += 4) {
                const float* wp = W + (size_t)(k0 + kq) * Dd + j;
                float w0 = 0.f, w1 = 0.f, w2 = 0.f, w3 = 0.f;
                if ((K % KB == 0) || (k0 + kq + 0 < K)) w0 = wp[0];
                if ((K % KB == 0) || (k0 + kq + 1 < K)) w1 = wp[Dd];
                if ((K % KB == 0) || (k0 + kq + 2 < K)) w2 = wp[2 * Dd];
                if ((K % KB == 0) || (k0 + kq + 3 < K)) w3 = wp[3 * Dd];
#pragma unroll
                for (int r = 0; r < TM; r++) {
                    float4 x4 = *reinterpret_cast<const float4*>(&xs[r][kq]);
                    acc[r] = fmaf(x4.x, w0, acc[r]);
                    acc[r] = fmaf(x4.y, w1, acc[r]);
                    acc[r] = fmaf(x4.z, w2, acc[r]);
                    acc[r] = fmaf(x4.w, w3, acc[r]);
                }
            }
        }
    }
    if (j < Dd) {
        float b = bias ? bias[j] : 0.f;
#pragma unroll
        for (int r = 0; r < TM; r++) {
            int row = row0 + r;
            if ((!GUARD) || (row < M))
                out[(size_t)row * Dd + j] = acc[r] + b;
        }
    }
}

// per-row quadratic forms -> sigmoid -> softmax weights -> scale out1/out2 in place
__global__ void __launch_bounds__(320, 2)
k_scalar(float* __restrict__ d_out) {
    constexpr int TM = 32;
    __shared__ float Psm[TM][304];
    __shared__ float red[10][TM];
    __shared__ float alphas[3][TM];
    __shared__ float fac[2][TM];
    const int tid = threadIdx.x;
    const int j = tid;
    const int lane = tid & 31, wrp = tid >> 5;
    const int row0 = blockIdx.x * TM;
    float* out0 = d_out;
    float* out1 = d_out + (size_t)Bn * Dd;
    float* out2 = d_out + 2 * (size_t)Bn * Dd;
    const float* srcs[3] = {out0, out1, out2};

    for (int z = 0; z < 3; z++) {
        __syncthreads();  // protect Psm / red reuse
        const float* src = srcs[z];
        for (int flat = tid; flat < TM * Dd; flat += 320) {
            int r = flat / Dd, c = flat % Dd;
            Psm[r][c] = src[(size_t)(row0 + r) * Dd + c];
        }
        __syncthreads();

        float acc[TM];
#pragma unroll
        for (int r = 0; r < TM; r++) acc[r] = 0.f;
        const float* A = g_A + z * Dd * Dd;
        if (j < Dd) {
            for (int i4 = 0; i4 < Dd; i4 += 4) {
                float a0 = A[(i4 + 0) * Dd + j];
                float a1 = A[(i4 + 1) * Dd + j];
                float a2 = A[(i4 + 2) * Dd + j];
                float a3 = A[(i4 + 3) * Dd + j];
#pragma unroll
                for (int r = 0; r < TM; r++) {
                    float4 p4 = *reinterpret_cast<const float4*>(&Psm[r][i4]);
                    acc[r] = fmaf(p4.x, a0, acc[r]);
                    acc[r] = fmaf(p4.y, a1, acc[r]);
                    acc[r] = fmaf(p4.z, a2, acc[r]);
                    acc[r] = fmaf(p4.w, a3, acc[r]);
                }
            }
        }
        float wj = (j < Dd) ? g_w[z * Dd + j] : 0.f;
#pragma unroll
        for (int r = 0; r < TM; r++) {
            float v = (j < Dd) ? (acc[r] + wj) * Psm[r][j] : 0.f;
#pragma unroll
            for (int off = 16; off > 0; off >>= 1)
                v += __shfl_xor_sync(0xffffffffu, v, off);
            if (lane == r) red[wrp][r] = v;   // all lanes hold warp sum after butterfly
        }
        __syncthreads();
        if (tid < TM) {
            float s = 0.f;
#pragma unroll
            for (int w = 0; w < 10; w++) s += red[w][tid];
            alphas[z][tid] = s + g_c[z];
        }
    }
    __syncthreads();
    if (tid < TM) {
        const float inv = 0.05773502691896258f;  // 1/sqrt(300)
        float zT = 1.f / (1.f + expf(-alphas[0][tid] * inv));
        float zI = 1.f / (1.f + expf(-alphas[1][tid] * inv));
        float zC = 1.f / (1.f + expf(-alphas[2][tid] * inv));
        // softmax over [zI*zT, zC*zT]: a1 = sigmoid(zT*(zI - zC))
        float a1 = 1.f / (1.f + expf(zT * (zC - zI)));
        fac[0][tid] = a1;
        fac[1][tid] = 1.f - a1;
    }
    __syncthreads();
    for (int flat = tid; flat < TM * Dd; flat += 320) {
        int r = flat / Dd, c = flat % Dd;
        size_t idx = (size_t)(row0 + r) * Dd + c;
        out1[idx] *= fac[0][r];
        out2[idx] *= fac[1][r];
    }
}

extern "C" void kernel_launch(void* const* d_in, const int* in_sizes, int n_in,
                              void* d_out, int out_size) {
    const float* T   = (const float*)d_in[0];
    const float* IM  = (const float*)d_in[1];
    const float* CD  = (const float*)d_in[2];
    const float* Wt  = (const float*)d_in[3];
    const float* bt  = (const float*)d_in[4];
    const float* Wim = (const float*)d_in[5];
    const float* bim = (const float*)d_in[6];
    const float* Wq[3] = {(const float*)d_in[7],  (const float*)d_in[11], (const float*)d_in[15]};
    const float* bq[3] = {(const float*)d_in[8],  (const float*)d_in[12], (const float*)d_in[16]};
    const float* Wk[3] = {(const float*)d_in[9],  (const float*)d_in[13], (const float*)d_in[17]};
    const float* bk[3] = {(const float*)d_in[10], (const float*)d_in[14], (const float*)d_in[18]};

    float *gWkT, *gA, *gw, *gc;
    cudaGetSymbolAddress((void**)&gWkT, g_WkT);
    cudaGetSymbolAddress((void**)&gA,   g_A);
    cudaGetSymbolAddress((void**)&gw,   g_w);
    cudaGetSymbolAddress((void**)&gc,   g_c);

    float* out  = (float*)d_out;
    float* out0 = out;
    float* out1 = out + (size_t)Bn * Dd;
    float* out2 = out + 2 * (size_t)Bn * Dd;

    const int tgrid = (Dd * Dd + 255) / 256;
    for (int z = 0; z < 3; z++) {
        k_transpose<<<tgrid, 256>>>(Wk[z], gWkT + z * Dd * Dd);
        k_wc<<<1, 320>>>(Wq[z], bq[z], Wk[z], bk[z], gw + z * Dd, gc + z);
    }
    // A_z = Wq_z @ Wk_z^T   (M=300, K=300)
    for (int z = 0; z < 3; z++)
        k_gemm<Dd, true><<<(Dd + 31) / 32, 320>>>(Wq[z], gWkT + z * Dd * Dd,
                                                  nullptr, gA + z * Dd * Dd, Dd);
    // projections (unscaled IM/CD written straight into output regions)
    k_gemm<Dt,  false><<<Bn / 32, 320>>>(T,  Wt,  bt,  out0, Bn);
    k_gemm<Dim, false><<<Bn / 32, 320>>>(IM, Wim, bim, out1, Bn);
    k_gemm<Dt,  false><<<Bn / 32, 320>>>(CD, Wt,  bt,  out2, Bn);
    // quadratic forms + sigmoid/softmax + in-place scaling
    k_scalar<<<Bn / 32, 320>>>(out);
}

// round 2
// speedup vs baseline: 1.0040x; 1.0040x over previous
#include <cuda_runtime.h>
#include <math.h>

#define Bn 65536
#define Dt 768
#define Dim 2048
#define Dd 300

// small precomputed scratch (allocation-free: __device__ globals)
__device__ float g_WkT[3 * Dd * Dd];
__device__ float g_A[3 * Dd * Dd];
__device__ float g_w[3 * Dd];
__device__ float g_c[3];

// transpose a [300,300] matrix: out[d*300+j] = in[j*300+d]
__global__ void k_transpose(const float* __restrict__ in, float* __restrict__ out) {
    int idx = blockIdx.x * 256 + threadIdx.x;
    if (idx < Dd * Dd) {
        int j = idx / Dd, d = idx % Dd;
        out[d * Dd + j] = in[idx];
    }
}

// w[i] = sum_d Wq[i,d]*bk[d] + Wk[i,d]*bq[d] ;  c = bq.bk
__global__ void k_wc(const float* __restrict__ Wq, const float* __restrict__ bq,
                     const float* __restrict__ Wk, const float* __restrict__ bk,
                     float* __restrict__ w_out, float* __restrict__ c_out) {
    int i = threadIdx.x;
    __shared__ float sred[320];
    if (i < Dd) {
        float s = 0.f;
        for (int d = 0; d < Dd; d++)
            s += Wq[i * Dd + d] * bk[d] + Wk[i * Dd + d] * bq[d];
        w_out[i] = s;
    }
    sred[i] = (i < Dd) ? bq[i] * bk[i] : 0.f;
    __syncthreads();
    for (int s = 256; s > 0; s >>= 1) {
        if (i < s && i + s < 320) sred[i] += sred[i + s];
        __syncthreads();
    }
    if (i == 0) *c_out = sred[0];
}

// out[M,300] = X[M,K] @ W[K,300] (+ bias). CTA: 32 rows x 300 cols, 320 threads.
template <int K, bool GUARD>
__global__ void __launch_bounds__(320, 2)
k_gemm(const float* __restrict__ X, const float* __restrict__ W,
       const float* __restrict__ bias, float* __restrict__ out, int M) {
    constexpr int TM = 32, KB = 32;
    __shared__ float xs[TM][KB];
    const int tid = threadIdx.x;
    const int j = tid;                 // output column
    const int row0 = blockIdx.x * TM;
    float acc[TM];
#pragma unroll
    for (int r = 0; r < TM; r++) acc[r] = 0.f;
    const int lr = tid >> 3, lk = (tid & 7) << 2;  // loader mapping (256 float4s)

    for (int k0 = 0; k0 < K; k0 += KB) {
        __syncthreads();
        if (tid < 256) {
            float4 v = make_float4(0.f, 0.f, 0.f, 0.f);
            int row = row0 + lr;
            bool okr = (!GUARD) || (row < M);
            bool okk = (K % KB == 0) || (k0 + lk < K);
            if (okr && okk)
                v = *reinterpret_cast<const float4*>(&X[(size_t)row * K + k0 + lk]);
            *reinterpret_cast<float4*>(&xs[lr][lk]) = v;
        }
        __syncthreads();
        if (j < Dd) {
#pragma unroll
            for (int kq = 0; kq < KB; kq += 4) {
                const float* wp = W + (size_t)(k0 + kq) * Dd + j;
                float w0 = 0.f, w1 = 0.f, w2 = 0.f, w3 = 0.f;
                if ((K % KB == 0) || (k0 + kq + 0 < K)) w0 = wp[0];
                if ((K % KB == 0) || (k0 + kq + 1 < K)) w1 = wp[Dd];
                if ((K % KB == 0) || (k0 + kq + 2 < K)) w2 = wp[2 * Dd];
                if ((K % KB == 0) || (k0 + kq + 3 < K)) w3 = wp[3 * Dd];
#pragma unroll
                for (int r = 0; r < TM; r++) {
                    float4 x4 = *reinterpret_cast<const float4*>(&xs[r][kq]);
                    acc[r] = fmaf(x4.x, w0, acc[r]);
                    acc[r] = fmaf(x4.y, w1, acc[r]);
                    acc[r] = fmaf(x4.z, w2, acc[r]);
                    acc[r] = fmaf(x4.w, w3, acc[r]);
                }
            }
        }
    }
    if (j < Dd) {
        float b = bias ? bias[j] : 0.f;
#pragma unroll
        for (int r = 0; r < TM; r++) {
            int row = row0 + r;
            if ((!GUARD) || (row < M))
                out[(size_t)row * Dd + j] = acc[r] + b;
        }
    }
}

// per-row quadratic forms -> sigmoid -> softmax weights -> scale out1/out2 in place
__global__ void __launch_bounds__(320, 2)
k_scalar(float* __restrict__ d_out) {
    constexpr int TM = 32;
    __shared__ float Psm[TM][304];
    __shared__ float red[10][TM];
    __shared__ float alphas[3][TM];
    __shared__ float fac[2][TM];
    const int tid = threadIdx.x;
    const int j = tid;
    const int lane = tid & 31, wrp = tid >> 5;
    const int row0 = blockIdx.x * TM;
    float* out0 = d_out;
    float* out1 = d_out + (size_t)Bn * Dd;
    float* out2 = d_out + 2 * (size_t)Bn * Dd;
    const float* srcs[3] = {out0, out1, out2};

    for (int z = 0; z < 3; z++) {
        __syncthreads();  // protect Psm / red reuse
        const float* src = srcs[z];
        for (int flat = tid; flat < TM * Dd; flat += 320) {
            int r = flat / Dd, c = flat % Dd;
            Psm[r][c] = src[(size_t)(row0 + r) * Dd + c];
        }
        __syncthreads();

        float acc[TM];
#pragma unroll
        for (int r = 0; r < TM; r++) acc[r] = 0.f;
        const float* A = g_A + z * Dd * Dd;
        if (j < Dd) {
            for (int i4 = 0; i4 < Dd; i4 += 4) {
                float a0 = A[(i4 + 0) * Dd + j];
                float a1 = A[(i4 + 1) * Dd + j];
                float a2 = A[(i4 + 2) * Dd + j];
                float a3 = A[(i4 + 3) * Dd + j];
#pragma unroll
                for (int r = 0; r < TM; r++) {
                    float4 p4 = *reinterpret_cast<const float4*>(&Psm[r][i4]);
                    acc[r] = fmaf(p4.x, a0, acc[r]);
                    acc[r] = fmaf(p4.y, a1, acc[r]);
                    acc[r] = fmaf(p4.z, a2, acc[r]);
                    acc[r] = fmaf(p4.w, a3, acc[r]);
                }
            }
        }
        float wj = (j < Dd) ? g_w[z * Dd + j] : 0.f;
#pragma unroll
        for (int r = 0; r < TM; r++) {
            float v = (j < Dd) ? (acc[r] + wj) * Psm[r][j] : 0.f;
#pragma unroll
            for (int off = 16; off > 0; off >>= 1)
                v += __shfl_xor_sync(0xffffffffu, v, off);
            if (lane == r) red[wrp][r] = v;   // all lanes hold warp sum after butterfly
        }
        __syncthreads();
        if (tid < TM) {
            float s = 0.f;
#pragma unroll
            for (int w = 0; w < 10; w++) s += red[w][tid];
            alphas[z][tid] = s + g_c[z];
        }
    }
    __syncthreads();
    if (tid < TM) {
        const float inv = 0.05773502691896258f;  // 1/sqrt(300)
        float zT = 1.f / (1.f + expf(-alphas[0][tid] * inv));
        float zI = 1.f / (1.f + expf(-alphas[1][tid] * inv));
        float zC = 1.f / (1.f + expf(-alphas[2][tid] * inv));
        // softmax over [zI*zT, zC*zT]: a1 = sigmoid(zT*(zI - zC))
        float a1 = 1.f / (1.f + expf(zT * (zC - zI)));
        fac[0][tid] = a1;
        fac[1][tid] = 1.f - a1;
    }
    __syncthreads();
    for (int flat = tid; flat < TM * Dd; flat += 320) {
        int r = flat / Dd, c = flat % Dd;
        size_t idx = (size_t)(row0 + r) * Dd + c;
        out1[idx] *= fac[0][r];
        out2[idx] *= fac[1][r];
    }
}

extern "C" void kernel_launch(void* const* d_in, const int* in_sizes, int n_in,
                              void* d_out, int out_size) {
    const float* T   = (const float*)d_in[0];
    const float* IM  = (const float*)d_in[1];
    const float* CD  = (const float*)d_in[2];
    const float* Wt  = (const float*)d_in[3];
    const float* bt  = (const float*)d_in[4];
    const float* Wim = (const float*)d_in[5];
    const float* bim = (const float*)d_in[6];
    const float* Wq[3] = {(const float*)d_in[7],  (const float*)d_in[11], (const float*)d_in[15]};
    const float* bq[3] = {(const float*)d_in[8],  (const float*)d_in[12], (const float*)d_in[16]};
    const float* Wk[3] = {(const float*)d_in[9],  (const float*)d_in[13], (const float*)d_in[17]};
    const float* bk[3] = {(const float*)d_in[10], (const float*)d_in[14], (const float*)d_in[18]};

    float *gWkT, *gA, *gw, *gc;
    cudaGetSymbolAddress((void**)&gWkT, g_WkT);
    cudaGetSymbolAddress((void**)&gA,   g_A);
    cudaGetSymbolAddress((void**)&gw,   g_w);
    cudaGetSymbolAddress((void**)&gc,   g_c);

    float* out  = (float*)d_out;
    float* out0 = out;
    float* out1 = out + (size_t)Bn * Dd;
    float* out2 = out + 2 * (size_t)Bn * Dd;

    const int tgrid = (Dd * Dd + 255) / 256;
    for (int z = 0; z < 3; z++) {
        k_transpose<<<tgrid, 256>>>(Wk[z], gWkT + z * Dd * Dd);
        k_wc<<<1, 320>>>(Wq[z], bq[z], Wk[z], bk[z], gw + z * Dd, gc + z);
    }
    // A_z = Wq_z @ Wk_z^T   (M=300, K=300)
    for (int z = 0; z < 3; z++)
        k_gemm<Dd, true><<<(Dd + 31) / 32, 320>>>(Wq[z], gWkT + z * Dd * Dd,
                                                  nullptr, gA + z * Dd * Dd, Dd);
    // projections (unscaled IM/CD written straight into output regions)
    k_gemm<Dt,  false><<<Bn / 32, 320>>>(T,  Wt,  bt,  out0, Bn);
    k_gemm<Dim, false><<<Bn / 32, 320>>>(IM, Wim, bim, out1, Bn);
    k_gemm<Dt,  false><<<Bn / 32, 320>>>(CD, Wt,  bt,  out2, Bn);
    // quadratic forms + sigmoid/softmax + in-place scaling
    k_scalar<<<Bn / 32, 320>>>(out);
}